// round 3
// baseline (speedup 1.0000x reference)
#include <cuda_runtime.h>

// Fold (col2im): x (8, 32, 8, 8, 4096) f32, kernel (8,8), stride (4,4),
// n = 64 -> out (8, 32, 260, 260) f32.
//
// Gather formulation: out[b,c,h,w] = sum over {p1,di : 4*p1+di==h, di<8, 0<=p1<64}
//                                        x {p2,dj : 4*p2+dj==w, dj<8, 0<=p2<64}
//                                    of x[b,c,di,dj,p1*64+p2]
// Since kernel/stride = 2, there are at most 2 (p1,di) branches and 2 (p2,dj)
// branches: (p1=h/4, di=h%4) and (p1=h/4-1, di=h%4+4), same for w.
//
// Each thread computes 4 consecutive w (one w-quad). All 4 share p2 in
// {wq, wq-1}; the dj offset equals the position within the quad. This makes
// every one of the <=16 loads per thread coalesced across the warp
// (consecutive threads -> consecutive p2), and the store a single float4.

#define B_   8
#define C_   32
#define Npat 64     // patch grid n
#define H_   260
#define W_   260
#define WQ   65     // W/4
#define LDIM 4096   // n*n

__global__ __launch_bounds__(256) void fold_gather_kernel(
    const float* __restrict__ x, float* __restrict__ out)
{
    const int TOTAL = B_ * C_ * H_ * WQ;   // 4,326,400 threads
    int idx = blockIdx.x * blockDim.x + threadIdx.x;
    if (idx >= TOTAL) return;

    int wq = idx % WQ;          // w-quad index: covers w = 4*wq .. 4*wq+3
    int t  = idx / WQ;
    int h  = t % H_;
    int bc = t / H_;            // b*C + c, 0..255

    const int r1 = h & 3;       // h % 4
    const int q1 = h >> 2;      // h / 4

    float acc0 = 0.f, acc1 = 0.f, acc2 = 0.f, acc3 = 0.f;

    const bool wA = (wq < Npat);   // dj = r (0..3), p2 = wq
    const bool wB = (wq >= 1);     // dj = r+4,      p2 = wq-1

    // ---- h-branch A: p1 = q1, di = r1 (valid while q1 < 64) ----
    if (q1 < Npat) {
        const float* base = x + (size_t)(bc * 8 + r1) * 8 * LDIM + q1 * Npat;
        if (wA) {
            acc0 += base[0 * LDIM + wq];
            acc1 += base[1 * LDIM + wq];
            acc2 += base[2 * LDIM + wq];
            acc3 += base[3 * LDIM + wq];
        }
        if (wB) {
            acc0 += base[4 * LDIM + wq - 1];
            acc1 += base[5 * LDIM + wq - 1];
            acc2 += base[6 * LDIM + wq - 1];
            acc3 += base[7 * LDIM + wq - 1];
        }
    }

    // ---- h-branch B: p1 = q1-1, di = r1+4 (valid while q1 >= 1) ----
    if (q1 >= 1) {
        const float* base = x + (size_t)(bc * 8 + r1 + 4) * 8 * LDIM + (q1 - 1) * Npat;
        if (wA) {
            acc0 += base[0 * LDIM + wq];
            acc1 += base[1 * LDIM + wq];
            acc2 += base[2 * LDIM + wq];
            acc3 += base[3 * LDIM + wq];
        }
        if (wB) {
            acc0 += base[4 * LDIM + wq - 1];
            acc1 += base[5 * LDIM + wq - 1];
            acc2 += base[6 * LDIM + wq - 1];
            acc3 += base[7 * LDIM + wq - 1];
        }
    }

    float4 v = make_float4(acc0, acc1, acc2, acc3);
    // out row base: ((bc)*H + h)*W + 4*wq ; W*4 bytes = 1040, 16B-aligned.
    *reinterpret_cast<float4*>(out + (size_t)(bc * H_ + h) * W_ + 4 * wq) = v;
}

extern "C" void kernel_launch(void* const* d_in, const int* in_sizes, int n_in,
                              void* d_out, int out_size)
{
    const float* x = (const float*)d_in[0];
    float* out = (float*)d_out;
    const int TOTAL = B_ * C_ * H_ * WQ;
    const int threads = 256;
    const int blocks = (TOTAL + threads - 1) / threads;
    fold_gather_kernel<<<blocks, threads>>>(x, out);
}